// round 11
// baseline (speedup 1.0000x reference)
#include <cuda_runtime.h>
#include <cuda_fp16.h>
#include <cstdint>

#define T_STEPS 2048
#define BATCH   128
#define DIM     100
#define HID     1024
#define NBLK    128         // 8 row-groups x 16 col-CTAs
#define NTH     288         // 8 compute warps (4 n-groups x 2 k-halves) + 1 comm warp
#define CCOL    64          // columns per CTA
#define CH_H    2176        // halfs per chunk image (16 rows x 136 pitch)
#define CH_B    4352        // bytes per chunk
#define APITCH  272         // bytes per A row (128 halfs + 8 pad)
#define WPITCH_H 1160       // halfs per W row (1152 + 8 pad)
#define WPITCH_B 2320

// ---- smem layout (bytes) ----
#define SA_OFF    0                      // 8 h-chunk slots: 34816
#define SX_OFF    34816                  // 2 x slots: 8704
#define SW_OFF    43520                  // W slice: 64*2320 = 148480
#define SBIAS_OFF 192000                 // 256
#define SPART_OFF 192256                 // partials: 2*4*1024 = 8192
#define SMB_OFF   200448                 // 20 mbars * 8 = 160
#define SMEM_TOTAL 200704

// mbar indices (each 8 bytes at MB + idx*8)
#define MB_FULL_H(j)  ((j))        // 0..7   tx-barriers, count 1
#define MB_FULL_X(p)  (8 + (p))    // 8..9   tx-barriers, count 1
#define MB_EMPTY_H(j) (10 + (j))   // 10..17 count 8 (one arrive per compute warp)
#define MB_EMPTY_X(p) (18 + (p))   // 18..19 count 8

// ---------------- device scratch ----------------
__device__ __align__(256) __half g_xT[(size_t)(T_STEPS + 1) * 8 * CH_H]; // [t][group][chunk-image]
__device__ __align__(256) __half g_h[2 * 8 * 8 * CH_H];                  // [buf][group][chunk][2176]
__device__ float  g_hlast[BATCH * HID];
__device__ unsigned g_cnt[8 * 16];       // [group][rank], +4 per step per CTA
__device__ unsigned g_bar_count;
__device__ unsigned g_bar_gen;

// ---------------- PTX helpers ----------------
__device__ __forceinline__ void ldsm_x4(uint32_t addr, uint32_t& r0, uint32_t& r1, uint32_t& r2, uint32_t& r3) {
    asm volatile("ldmatrix.sync.aligned.m8n8.x4.shared.b16 {%0,%1,%2,%3}, [%4];\n"
                 : "=r"(r0), "=r"(r1), "=r"(r2), "=r"(r3) : "r"(addr));
}
__device__ __forceinline__ void mma16816(float* c, uint32_t a0, uint32_t a1, uint32_t a2, uint32_t a3,
                                         uint32_t b0, uint32_t b1) {
    asm volatile("mma.sync.aligned.m16n8k16.row.col.f32.f16.f16.f32 "
                 "{%0,%1,%2,%3},{%4,%5,%6,%7},{%8,%9},{%0,%1,%2,%3};\n"
                 : "+f"(c[0]), "+f"(c[1]), "+f"(c[2]), "+f"(c[3])
                 : "r"(a0), "r"(a1), "r"(a2), "r"(a3), "r"(b0), "r"(b1));
}
__device__ __forceinline__ unsigned ld_acq(const unsigned* p) {
    unsigned v;
    asm volatile("ld.acquire.gpu.u32 %0, [%1];" : "=r"(v) : "l"(p) : "memory");
    return v;
}
__device__ __forceinline__ void mbar_init(uint32_t mbar, uint32_t cnt) {
    asm volatile("mbarrier.init.shared.b64 [%0], %1;" :: "r"(mbar), "r"(cnt) : "memory");
}
__device__ __forceinline__ void mbar_expect_tx(uint32_t mbar, uint32_t bytes) {
    asm volatile("mbarrier.arrive.expect_tx.shared.b64 _, [%0], %1;" :: "r"(mbar), "r"(bytes) : "memory");
}
__device__ __forceinline__ void mbar_arrive(uint32_t mbar) {
    asm volatile("mbarrier.arrive.shared.b64 _, [%0];" :: "r"(mbar) : "memory");
}
__device__ __forceinline__ void bulk_g2s(uint32_t dst, const void* src, uint32_t bytes, uint32_t mbar) {
    asm volatile("cp.async.bulk.shared::cluster.global.mbarrier::complete_tx::bytes [%0], [%1], %2, [%3];"
                 :: "r"(dst), "l"(src), "r"(bytes), "r"(mbar) : "memory");
}
__device__ __forceinline__ void mbar_wait(uint32_t mbar, uint32_t parity) {
    uint32_t done;
    do {
        asm volatile("{\n\t.reg .pred p;\n\t"
                     "mbarrier.try_wait.parity.acquire.cta.shared::cta.b64 p, [%1], %2, 0x989680;\n\t"
                     "selp.b32 %0, 1, 0, p;\n\t}"
                     : "=r"(done) : "r"(mbar), "r"(parity) : "memory");
    } while (!done);
}

// ---------------- grid barrier (init/final only) ----------------
__device__ __forceinline__ void grid_barrier() {
    __syncthreads();
    if (threadIdx.x == 0) {
        unsigned my = *(volatile unsigned*)&g_bar_gen;
        __threadfence();
        unsigned a = atomicAdd(&g_bar_count, 1u);
        if (a == NBLK - 1) {
            *(volatile unsigned*)&g_bar_count = 0u;
            __threadfence();
            atomicAdd(&g_bar_gen, 1u);
        } else {
            while (*(volatile unsigned*)&g_bar_gen == my) { __nanosleep(40); }
        }
        __threadfence();
    }
    __syncthreads();
}

// ---------------- kernel 1: x -> [t][group][16 rows x 136 pitch] fp16 ----------------
__global__ void __launch_bounds__(256) xform_kernel(const float* __restrict__ x) {
    int t = blockIdx.x;
    __half* o = g_xT + (size_t)t * 8 * CH_H;
    for (int i = threadIdx.x; i < 8 * CH_H; i += 256) {
        int g = i / CH_H, idx = i % CH_H;
        int row = idx / 136, k = idx % 136;
        float v = 0.0f;
        if (t < T_STEPS && k < DIM)
            v = x[((size_t)t * BATCH + (16 * g + row)) * DIM + k];
        o[i] = __float2half_rn(v);
    }
}

// ---------------- kernel 2: persistent RNN, comm-warp pipelined ----------------
__global__ void __launch_bounds__(NTH, 1)
rnn_kernel(const float* __restrict__ W_ih, const float* __restrict__ b_ih,
           const float* __restrict__ W_hh, const float* __restrict__ b_hh,
           const float* __restrict__ W_out, const float* __restrict__ b_out,
           float* __restrict__ out)
{
    extern __shared__ char smem[];
    __half* sW    = (__half*)(smem + SW_OFF);
    float*  sBias = (float*)(smem + SBIAS_OFF);
    float*  sPart = (float*)(smem + SPART_OFF);

    const int tid  = threadIdx.x;
    const int blk  = blockIdx.x;
    const int g    = blk >> 4;       // row group: batch rows [16g, 16g+16)
    const int r    = blk & 15;       // rank: cols [64r, 64r+64)
    const int rot  = r & 7;          // rotated chunk start
    const int lane = tid & 31;
    const int warp = tid >> 5;       // 0..7 compute, 8 comm

    uint32_t smem_u = (uint32_t)__cvta_generic_to_shared(smem);
    const uint32_t MB = smem_u + SMB_OFF;

    // ---- prologue: W slice (zero pads then fill) ----
    for (int i = tid; i < (CCOL * WPITCH_B) / 4; i += NTH)
        ((uint32_t*)sW)[i] = 0u;
    __syncthreads();
    for (int i = tid; i < CCOL * HID; i += NTH) {
        int n = i >> 10, k = i & 1023;
        sW[n * WPITCH_H + k] = __float2half_rn(W_hh[(64 * r + n) * HID + k]);
    }
    for (int i = tid; i < CCOL * DIM; i += NTH) {
        int n = i / DIM, d = i % DIM;
        sW[n * WPITCH_H + HID + d] = __float2half_rn(W_ih[(64 * r + n) * DIM + d]);
    }
    if (tid < CCOL) sBias[tid] = b_ih[64 * r + tid] + b_hh[64 * r + tid];

    // zero h buf 0 (incl pads): 17408 uint4 over 128*288 threads
    {
        int i = blk * NTH + tid;
        if (i < 17408) ((uint4*)g_h)[i] = make_uint4(0u, 0u, 0u, 0u);
    }
    if (tid == 0) {
        #pragma unroll
        for (int j = 0; j < 8; ++j) { mbar_init(MB + MB_FULL_H(j) * 8, 1); mbar_init(MB + MB_EMPTY_H(j) * 8, 8); }
        #pragma unroll
        for (int p = 0; p < 2; ++p) { mbar_init(MB + MB_FULL_X(p) * 8, 1); mbar_init(MB + MB_EMPTY_X(p) * 8, 8); }
    }
    grid_barrier();

    // prologue bulk issues: x0, x1, h(0) chunks in rotated order (slot j <- chunk (rot+j)&7)
    if (tid == 0) {
        mbar_expect_tx(MB + MB_FULL_X(0) * 8, CH_B);
        bulk_g2s(smem_u + SX_OFF, &g_xT[(size_t)0 * 8 * CH_H + g * CH_H], CH_B, MB + MB_FULL_X(0) * 8);
        mbar_expect_tx(MB + MB_FULL_X(1) * 8, CH_B);
        bulk_g2s(smem_u + SX_OFF + CH_B, &g_xT[(size_t)1 * 8 * CH_H + g * CH_H], CH_B, MB + MB_FULL_X(1) * 8);
        #pragma unroll
        for (int j = 0; j < 8; ++j) {
            const int cj = (rot + j) & 7;
            mbar_expect_tx(MB + MB_FULL_H(j) * 8, CH_B);
            bulk_g2s(smem_u + SA_OFF + j * CH_B, &g_h[(size_t)(0 * 8 + g) * 8 * CH_H + cj * CH_H], CH_B, MB + MB_FULL_H(j) * 8);
        }
    }

    unsigned* mycnt = &g_cnt[g * 16 + r];
    const unsigned* pollbase = &g_cnt[g * 16];

    if (warp == 8) {
        // ================= comm warp: issue step t+1 while step t computes ===========
        for (int t = 0; t < T_STEPS - 1; ++t) {
            const unsigned tgt = 4u * (unsigned)(t + 1);
            const int nb = (t + 1) & 1;
            // x for step t+2 (slot t&1, after consumers drained it at step t)
            if (t + 2 < T_STEPS) {
                mbar_wait(MB + MB_EMPTY_X(t & 1) * 8, (unsigned)((t >> 1) & 1));
                if (lane == 0) {
                    mbar_expect_tx(MB + MB_FULL_X(t & 1) * 8, CH_B);
                    bulk_g2s(smem_u + SX_OFF + (t & 1) * CH_B,
                             &g_xT[(size_t)(t + 2) * 8 * CH_H + g * CH_H], CH_B, MB + MB_FULL_X(t & 1) * 8);
                }
            }
            unsigned pmask = 0u;
            #pragma unroll
            for (int j = 0; j < 8; ++j) {
                const int cj = (rot + j) & 7;
                mbar_wait(MB + MB_EMPTY_H(j) * 8, (unsigned)(t & 1));   // consumers drained slot j (step t)
                while (!((pmask >> cj) & 1u)) {                          // producers of chunk cj published step t
                    unsigned v = (lane < 16) ? ld_acq(pollbase + lane) : tgt;
                    unsigned b = __ballot_sync(0xFFFFFFFFu, v >= tgt);
                    unsigned pr = b & (b >> 1);
                    unsigned m = 0u;
                    #pragma unroll
                    for (int p = 0; p < 8; ++p) m |= ((pr >> (2 * p)) & 1u) << p;
                    pmask |= m;
                }
                if (lane == 0) {
                    mbar_expect_tx(MB + MB_FULL_H(j) * 8, CH_B);
                    bulk_g2s(smem_u + SA_OFF + j * CH_B,
                             &g_h[(size_t)(nb * 8 + g) * 8 * CH_H + cj * CH_H], CH_B, MB + MB_FULL_H(j) * 8);
                }
            }
        }
    } else {
        // ================= compute warps =================
        const int nw   = warp & 3;       // n-group: local cols [16nw, 16nw+16)
        const int ks   = warp >> 2;      // k-half
        const uint32_t aoff = (lane & 15) * APITCH + ((lane >> 4) * 16) + ks * 128;
        const uint32_t boff = smem_u + SW_OFF
            + (16 * nw + (lane & 7) + ((lane & 16) >> 1)) * WPITCH_B
            + (((lane >> 3) & 1) * 16) + ks * 128;
        const int er  = lane >> 2;
        const int ecc = 2 * (lane & 3);

        for (int t = 0; t < T_STEPS; ++t) {
            float acc[8];
            #pragma unroll
            for (int i = 0; i < 8; ++i) acc[i] = 0.0f;

            // x chunk
            mbar_wait(MB + MB_FULL_X(t & 1) * 8, (unsigned)((t >> 1) & 1));
            {
                uint32_t ab = smem_u + SX_OFF + (t & 1) * CH_B + aoff;
                uint32_t bb = boff + 2048;
                #pragma unroll
                for (int s = 0; s < 4; ++s) {
                    uint32_t a0, a1, a2, a3, b0, b1, b2, b3;
                    ldsm_x4(bb + s * 32, b0, b1, b2, b3);
                    ldsm_x4(ab + s * 32, a0, a1, a2, a3);
                    mma16816(acc + 0, a0, a1, a2, a3, b0, b1);
                    mma16816(acc + 4, a0, a1, a2, a3, b2, b3);
                }
            }
            if (lane == 0) mbar_arrive(MB + MB_EMPTY_X(t & 1) * 8);

            // h chunks in rotated order
            #pragma unroll
            for (int j = 0; j < 8; ++j) {
                const int cj = (rot + j) & 7;
                mbar_wait(MB + MB_FULL_H(j) * 8, (unsigned)(t & 1));
                uint32_t ab = smem_u + SA_OFF + j * CH_B + aoff;
                uint32_t bb = boff + cj * 256;
                #pragma unroll
                for (int s = 0; s < 4; ++s) {
                    uint32_t a0, a1, a2, a3, b0, b1, b2, b3;
                    ldsm_x4(bb + s * 32, b0, b1, b2, b3);
                    ldsm_x4(ab + s * 32, a0, a1, a2, a3);
                    mma16816(acc + 0, a0, a1, a2, a3, b0, b1);
                    mma16816(acc + 4, a0, a1, a2, a3, b2, b3);
                }
                if (lane == 0) mbar_arrive(MB + MB_EMPTY_H(j) * 8);
            }

            if (warp >= 4) {
                float* p = sPart + (t & 1) * 1024 + nw * 256 + lane * 8;
                *reinterpret_cast<float4*>(p)     = make_float4(acc[0], acc[1], acc[2], acc[3]);
                *reinterpret_cast<float4*>(p + 4) = make_float4(acc[4], acc[5], acc[6], acc[7]);
                __threadfence_block();
                asm volatile("bar.arrive 1, 256;" ::: "memory");
            } else {
                asm volatile("bar.sync 1, 256;" ::: "memory");
                const float* p = sPart + (t & 1) * 1024 + nw * 256 + lane * 8;
                float4 q0 = *reinterpret_cast<const float4*>(p);
                float4 q1 = *reinterpret_cast<const float4*>(p + 4);

                const int jl = 16 * nw + ecc;
                const float bi0 = sBias[jl], bi1 = sBias[jl + 1];
                const float bi4 = sBias[jl + 8], bi5 = sBias[jl + 9];
                float h0 = tanhf(acc[0] + q0.x + bi0);
                float h1 = tanhf(acc[1] + q0.y + bi1);
                float h2 = tanhf(acc[2] + q0.z + bi0);
                float h3 = tanhf(acc[3] + q0.w + bi1);
                float h4 = tanhf(acc[4] + q1.x + bi4);
                float h5 = tanhf(acc[5] + q1.y + bi5);
                float h6 = tanhf(acc[6] + q1.z + bi4);
                float h7 = tanhf(acc[7] + q1.w + bi5);

                const int jc = 64 * r + jl;
                const int ch = jc >> 7, cc = jc & 127;
                __half* hb = g_h + (size_t)(((t + 1) & 1) * 8 + g) * 8 * CH_H + ch * CH_H;
                *reinterpret_cast<__half2*>(&hb[er * 136 + cc])           = __floats2half2_rn(h0, h1);
                *reinterpret_cast<__half2*>(&hb[(er + 8) * 136 + cc])     = __floats2half2_rn(h2, h3);
                *reinterpret_cast<__half2*>(&hb[er * 136 + cc + 8])       = __floats2half2_rn(h4, h5);
                *reinterpret_cast<__half2*>(&hb[(er + 8) * 136 + cc + 8]) = __floats2half2_rn(h6, h7);
                if (t == T_STEPS - 1) {
                    int gr0 = 16 * g + er, gr1 = gr0 + 8;
                    g_hlast[gr0 * HID + jc]     = h0;
                    g_hlast[gr0 * HID + jc + 1] = h1;
                    g_hlast[gr1 * HID + jc]     = h2;
                    g_hlast[gr1 * HID + jc + 1] = h3;
                    g_hlast[gr0 * HID + jc + 8] = h4;
                    g_hlast[gr0 * HID + jc + 9] = h5;
                    g_hlast[gr1 * HID + jc + 8] = h6;
                    g_hlast[gr1 * HID + jc + 9] = h7;
                }
                __syncwarp();
                if (lane == 0)
                    asm volatile("red.release.gpu.global.add.u32 [%0], %1;"
                                 :: "l"(mycnt), "r"(1u) : "memory");
            }
        }
    }

    // ---- drain, reset counters, readout ----
    grid_barrier();
    if (blk == 0) {
        if (tid < 128) g_cnt[tid] = 0u;
        if (warp < 8) {
            for (int b = warp; b < BATCH; b += 8) {
                float a = 0.0f;
                #pragma unroll 4
                for (int j = lane; j < HID; j += 32)
                    a += g_hlast[b * HID + j] * W_out[j];
                #pragma unroll
                for (int o = 16; o; o >>= 1) a += __shfl_xor_sync(0xFFFFFFFFu, a, o);
                if (lane == 0) out[b] = tanhf(a + b_out[0]);
            }
        }
    }
}

// ---------------- launch ----------------
extern "C" void kernel_launch(void* const* d_in, const int* in_sizes, int n_in,
                              void* d_out, int out_size) {
    const float* x     = (const float*)d_in[0];
    const float* W_ih  = (const float*)d_in[1];
    const float* b_ih  = (const float*)d_in[2];
    const float* W_hh  = (const float*)d_in[3];
    const float* b_hh  = (const float*)d_in[4];
    const float* W_out = (const float*)d_in[5];
    const float* b_out = (const float*)d_in[6];

    cudaFuncSetAttribute(rnn_kernel, cudaFuncAttributeMaxDynamicSharedMemorySize, SMEM_TOTAL);

    xform_kernel<<<T_STEPS + 1, 256>>>(x);
    rnn_kernel<<<NBLK, NTH, SMEM_TOTAL>>>(W_ih, b_ih, W_hh, b_hh, W_out, b_out, (float*)d_out);
}

// round 14
// speedup vs baseline: 1.2597x; 1.2597x over previous
#include <cuda_runtime.h>
#include <cuda_fp16.h>
#include <cstdint>

#define T_STEPS 2048
#define BATCH   128
#define DIM     100
#define HID     1024
#define NBLK    128         // 8 row-groups x 16 col-CTAs
#define NTH     256         // 8 warps: 4 n-groups x 2 k-halves
#define CCOL    64          // columns per CTA
#define CH_H    2176        // halfs per chunk image (16 rows x 136 pitch)
#define CH_B    4352        // bytes per chunk
#define APITCH  272         // bytes per A row (128 halfs + 8 pad)
#define WPITCH_H 1160       // halfs per W row (1152 + 8 pad)
#define WPITCH_B 2320

// ---- smem layout (bytes) ----
#define SA_OFF    0                      // 8 h-chunk slots: 34816
#define SX_OFF    34816                  // 2 x slots: 8704
#define SW_OFF    43520                  // W slice: 64*2320 = 148480
#define SBIAS_OFF 192000                 // 256
#define SPART_OFF 192256                 // partials: 2*4*1024 = 8192
#define SMB_OFF   200448                 // 10 mbars * 8
#define SMEM_TOTAL 200704

// ---------------- device scratch ----------------
__device__ __align__(256) __half g_xT[(size_t)(T_STEPS + 1) * 8 * CH_H]; // [t][group][chunk-image]
__device__ __align__(256) __half g_h[2 * 8 * 8 * CH_H];                  // [buf][group][chunk][2176]
__device__ float  g_hlast[BATCH * HID];
__device__ unsigned g_cnt[8 * 16];       // [group][rank], +4 per step per CTA
__device__ unsigned g_bar_count;
__device__ unsigned g_bar_gen;

// ---------------- PTX helpers ----------------
__device__ __forceinline__ void ldsm_x4(uint32_t addr, uint32_t& r0, uint32_t& r1, uint32_t& r2, uint32_t& r3) {
    asm volatile("ldmatrix.sync.aligned.m8n8.x4.shared.b16 {%0,%1,%2,%3}, [%4];\n"
                 : "=r"(r0), "=r"(r1), "=r"(r2), "=r"(r3) : "r"(addr));
}
__device__ __forceinline__ void mma16816(float* c, uint32_t a0, uint32_t a1, uint32_t a2, uint32_t a3,
                                         uint32_t b0, uint32_t b1) {
    asm volatile("mma.sync.aligned.m16n8k16.row.col.f32.f16.f16.f32 "
                 "{%0,%1,%2,%3},{%4,%5,%6,%7},{%8,%9},{%0,%1,%2,%3};\n"
                 : "+f"(c[0]), "+f"(c[1]), "+f"(c[2]), "+f"(c[3])
                 : "r"(a0), "r"(a1), "r"(a2), "r"(a3), "r"(b0), "r"(b1));
}
__device__ __forceinline__ unsigned ld_acq(const unsigned* p) {
    unsigned v;
    asm volatile("ld.acquire.gpu.u32 %0, [%1];" : "=r"(v) : "l"(p) : "memory");
    return v;
}
__device__ __forceinline__ void mbar_init(uint32_t mbar, uint32_t cnt) {
    asm volatile("mbarrier.init.shared.b64 [%0], %1;" :: "r"(mbar), "r"(cnt) : "memory");
}
__device__ __forceinline__ void mbar_expect_tx(uint32_t mbar, uint32_t bytes) {
    asm volatile("mbarrier.arrive.expect_tx.shared.b64 _, [%0], %1;" :: "r"(mbar), "r"(bytes) : "memory");
}
__device__ __forceinline__ void bulk_g2s(uint32_t dst, const void* src, uint32_t bytes, uint32_t mbar) {
    asm volatile("cp.async.bulk.shared::cluster.global.mbarrier::complete_tx::bytes [%0], [%1], %2, [%3];"
                 :: "r"(dst), "l"(src), "r"(bytes), "r"(mbar) : "memory");
}
__device__ __forceinline__ void mbar_wait(uint32_t mbar, uint32_t parity) {
    uint32_t done;
    do {
        asm volatile("{\n\t.reg .pred p;\n\t"
                     "mbarrier.try_wait.parity.acquire.cta.shared::cta.b64 p, [%1], %2, 0x989680;\n\t"
                     "selp.b32 %0, 1, 0, p;\n\t}"
                     : "=r"(done) : "r"(mbar), "r"(parity) : "memory");
    } while (!done);
}

// ---------------- grid barrier (init/final only) ----------------
__device__ __forceinline__ void grid_barrier() {
    __syncthreads();
    if (threadIdx.x == 0) {
        unsigned my = *(volatile unsigned*)&g_bar_gen;
        __threadfence();
        unsigned a = atomicAdd(&g_bar_count, 1u);
        if (a == NBLK - 1) {
            *(volatile unsigned*)&g_bar_count = 0u;
            __threadfence();
            atomicAdd(&g_bar_gen, 1u);
        } else {
            while (*(volatile unsigned*)&g_bar_gen == my) { __nanosleep(40); }
        }
        __threadfence();
    }
    __syncthreads();
}

// ---------------- kernel 1: x -> [t][group][16 rows x 136 pitch] fp16 ----------------
__global__ void __launch_bounds__(256) xform_kernel(const float* __restrict__ x) {
    int t = blockIdx.x;
    __half* o = g_xT + (size_t)t * 8 * CH_H;
    for (int i = threadIdx.x; i < 8 * CH_H; i += 256) {
        int g = i / CH_H, idx = i % CH_H;
        int row = idx / 136, k = idx % 136;
        float v = 0.0f;
        if (t < T_STEPS && k < DIM)
            v = x[((size_t)t * BATCH + (16 * g + row)) * DIM + k];
        o[i] = __float2half_rn(v);
    }
}

// ---------------- kernel 2: persistent RNN, register-resident W ----------------
__global__ void __launch_bounds__(NTH, 1)
rnn_kernel(const float* __restrict__ W_ih, const float* __restrict__ b_ih,
           const float* __restrict__ W_hh, const float* __restrict__ b_hh,
           const float* __restrict__ W_out, const float* __restrict__ b_out,
           float* __restrict__ out)
{
    extern __shared__ char smem[];
    __half* sW    = (__half*)(smem + SW_OFF);
    float*  sBias = (float*)(smem + SBIAS_OFF);
    float*  sPart = (float*)(smem + SPART_OFF);

    const int tid  = threadIdx.x;
    const int blk  = blockIdx.x;
    const int g    = blk >> 4;       // row group: batch rows [16g, 16g+16)
    const int r    = blk & 15;       // rank: cols [64r, 64r+64)
    const int rot  = r & 7;          // rotated chunk start
    const int lane = tid & 31;
    const int warp = tid >> 5;       // 8 warps
    const int nw   = warp & 3;       // n-group: local cols [16nw, 16nw+16)
    const int ks   = warp >> 2;      // k-half within each 128-k chunk

    uint32_t smem_u = (uint32_t)__cvta_generic_to_shared(smem);
    const uint32_t MB = smem_u + SMB_OFF;     // h mbars 0..7 (by slot), x mbars 8,9

    // ---- prologue: W slice (zero pads then fill) ----
    for (int i = tid; i < (CCOL * WPITCH_B) / 4; i += NTH)
        ((uint32_t*)sW)[i] = 0u;
    __syncthreads();
    for (int i = tid; i < CCOL * HID; i += NTH) {
        int n = i >> 10, k = i & 1023;
        sW[n * WPITCH_H + k] = __float2half_rn(W_hh[(64 * r + n) * HID + k]);
    }
    for (int i = tid; i < CCOL * DIM; i += NTH) {
        int n = i / DIM, d = i % DIM;
        sW[n * WPITCH_H + HID + d] = __float2half_rn(W_ih[(64 * r + n) * DIM + d]);
    }
    if (tid < CCOL) sBias[tid] = b_ih[64 * r + tid] + b_hh[64 * r + tid];

    // zero h buf 0 (incl pads): 17408 uint4 over 32768 threads
    {
        int i = blk * NTH + tid;
        if (i < 17408) ((uint4*)g_h)[i] = make_uint4(0u, 0u, 0u, 0u);
    }
    if (tid == 0) {
        #pragma unroll
        for (int m = 0; m < 10; ++m) mbar_init(MB + m * 8, 1);
    }

    // ---- per-warp addressing ----
    const uint32_t aoff = (lane & 15) * APITCH + ((lane >> 4) * 16) + ks * 128;
    const uint32_t boff = smem_u + SW_OFF
        + (16 * nw + (lane & 7) + ((lane & 16) >> 1)) * WPITCH_B
        + (((lane >> 3) & 1) * 16) + ks * 128;

    // ---- hoist B (weights) into registers: 9 "chunks" x 16 regs, in consumption order ----
    // jj = 0 -> x slice; jj = 1..8 -> h slot j = jj-1 (chunk (rot+j-1)&7)
    __syncthreads();   // W smem fill complete
    uint32_t breg[144];
    #pragma unroll
    for (int jj = 0; jj < 9; ++jj) {
        uint32_t bb = (jj == 0) ? (boff + 2048) : (boff + (((rot + jj - 1) & 7) * 256));
        #pragma unroll
        for (int s = 0; s < 4; ++s)
            ldsm_x4(bb + s * 32, breg[jj * 16 + s * 4 + 0], breg[jj * 16 + s * 4 + 1],
                                 breg[jj * 16 + s * 4 + 2], breg[jj * 16 + s * 4 + 3]);
    }

    grid_barrier();

    // prologue bulk issues: x0, x1, h(0) chunks in rotated order (slot j <- chunk (rot+j)&7)
    if (tid == 0) {
        mbar_expect_tx(MB + 8 * 8, CH_B);
        bulk_g2s(smem_u + SX_OFF, &g_xT[(size_t)0 * 8 * CH_H + g * CH_H], CH_B, MB + 8 * 8);
        mbar_expect_tx(MB + 9 * 8, CH_B);
        bulk_g2s(smem_u + SX_OFF + CH_B, &g_xT[(size_t)1 * 8 * CH_H + g * CH_H], CH_B, MB + 9 * 8);
        #pragma unroll
        for (int j = 0; j < 8; ++j) {
            const int cj = (rot + j) & 7;
            mbar_expect_tx(MB + j * 8, CH_B);
            bulk_g2s(smem_u + SA_OFF + j * CH_B, &g_h[(size_t)(0 * 8 + g) * 8 * CH_H + cj * CH_H], CH_B, MB + j * 8);
        }
    }

    const int er  = lane >> 2;
    const int ecc = 2 * (lane & 3);
    unsigned* mycnt = &g_cnt[g * 16 + r];
    const unsigned* pollbase = &g_cnt[g * 16];

    // ---- time loop ----
    for (int t = 0; t < T_STEPS; ++t) {
        float acc[8];
        #pragma unroll
        for (int i = 0; i < 8; ++i) acc[i] = 0.0f;

        // x chunk (prefetched one step ahead), B from breg[0..15]
        mbar_wait(MB + (8 + (t & 1)) * 8, (unsigned)((t >> 1) & 1));
        {
            uint32_t ab = smem_u + SX_OFF + (t & 1) * CH_B + aoff;
            #pragma unroll
            for (int s = 0; s < 4; ++s) {
                uint32_t a0, a1, a2, a3;
                ldsm_x4(ab + s * 32, a0, a1, a2, a3);
                mma16816(acc + 0, a0, a1, a2, a3, breg[s * 4 + 0], breg[s * 4 + 1]);
                mma16816(acc + 4, a0, a1, a2, a3, breg[s * 4 + 2], breg[s * 4 + 3]);
            }
        }

        // h chunks in rotated order, gated by slot mbars; B from breg[(j+1)*16...]
        #pragma unroll
        for (int j = 0; j < 8; ++j) {
            mbar_wait(MB + j * 8, (unsigned)(t & 1));
            uint32_t ab = smem_u + SA_OFF + j * CH_B + aoff;
            #pragma unroll
            for (int s = 0; s < 4; ++s) {
                uint32_t a0, a1, a2, a3;
                ldsm_x4(ab + s * 32, a0, a1, a2, a3);
                mma16816(acc + 0, a0, a1, a2, a3, breg[(j + 1) * 16 + s * 4 + 0], breg[(j + 1) * 16 + s * 4 + 1]);
                mma16816(acc + 4, a0, a1, a2, a3, breg[(j + 1) * 16 + s * 4 + 2], breg[(j + 1) * 16 + s * 4 + 3]);
            }
        }

        if (warp >= 4) {
            // store partials, arrive (non-blocking), race ahead
            float* p = sPart + (t & 1) * 1024 + nw * 256 + lane * 8;
            *reinterpret_cast<float4*>(p)     = make_float4(acc[0], acc[1], acc[2], acc[3]);
            *reinterpret_cast<float4*>(p + 4) = make_float4(acc[4], acc[5], acc[6], acc[7]);
            __threadfence_block();
            asm volatile("bar.arrive 1, 256;" ::: "memory");
        } else {
            asm volatile("bar.sync 1, 256;" ::: "memory");
            const float* p = sPart + (t & 1) * 1024 + nw * 256 + lane * 8;
            float4 q0 = *reinterpret_cast<const float4*>(p);
            float4 q1 = *reinterpret_cast<const float4*>(p + 4);

            const int jl = 16 * nw + ecc;             // local col
            const float bi0 = sBias[jl], bi1 = sBias[jl + 1];
            const float bi4 = sBias[jl + 8], bi5 = sBias[jl + 9];
            float h0 = tanhf(acc[0] + q0.x + bi0);
            float h1 = tanhf(acc[1] + q0.y + bi1);
            float h2 = tanhf(acc[2] + q0.z + bi0);
            float h3 = tanhf(acc[3] + q0.w + bi1);
            float h4 = tanhf(acc[4] + q1.x + bi4);
            float h5 = tanhf(acc[5] + q1.y + bi5);
            float h6 = tanhf(acc[6] + q1.z + bi4);
            float h7 = tanhf(acc[7] + q1.w + bi5);

            const int jc = 64 * r + jl;               // global col
            const int ch = jc >> 7, cc = jc & 127;
            __half* hb = g_h + (size_t)(((t + 1) & 1) * 8 + g) * 8 * CH_H + ch * CH_H;
            *reinterpret_cast<__half2*>(&hb[er * 136 + cc])           = __floats2half2_rn(h0, h1);
            *reinterpret_cast<__half2*>(&hb[(er + 8) * 136 + cc])     = __floats2half2_rn(h2, h3);
            *reinterpret_cast<__half2*>(&hb[er * 136 + cc + 8])       = __floats2half2_rn(h4, h5);
            *reinterpret_cast<__half2*>(&hb[(er + 8) * 136 + cc + 8]) = __floats2half2_rn(h6, h7);
            if (t == T_STEPS - 1) {
                int gr0 = 16 * g + er, gr1 = gr0 + 8;
                g_hlast[gr0 * HID + jc]     = h0;
                g_hlast[gr0 * HID + jc + 1] = h1;
                g_hlast[gr1 * HID + jc]     = h2;
                g_hlast[gr1 * HID + jc + 1] = h3;
                g_hlast[gr0 * HID + jc + 8] = h4;
                g_hlast[gr0 * HID + jc + 9] = h5;
                g_hlast[gr1 * HID + jc + 8] = h6;
                g_hlast[gr1 * HID + jc + 9] = h7;
            }
            __syncwarp();
            if (lane == 0)
                asm volatile("red.release.gpu.global.add.u32 [%0], %1;"
                             :: "l"(mycnt), "r"(1u) : "memory");

            // warp 0: per-chunk gated issue of next step's bulks
            if (warp == 0 && t + 1 < T_STEPS) {
                const unsigned tgt = 4u * (unsigned)(t + 1);
                const int nb = (t + 1) & 1;
                // x bulk first (no dependency)
                if (lane == 0) {
                    mbar_expect_tx(MB + (8 + (t & 1)) * 8, CH_B);
                    bulk_g2s(smem_u + SX_OFF + (t & 1) * CH_B,
                             &g_xT[(size_t)(t + 2) * 8 * CH_H + g * CH_H], CH_B, MB + (8 + (t & 1)) * 8);
                }
                unsigned pmask = 0u;   // bit c: chunk c's producer pair (ranks 2c,2c+1) ready
                #pragma unroll
                for (int j = 0; j < 8; ++j) {
                    const int cj = (rot + j) & 7;
                    while (!((pmask >> cj) & 1u)) {
                        unsigned v = (lane < 16) ? ld_acq(pollbase + lane) : tgt;
                        unsigned b = __ballot_sync(0xFFFFFFFFu, v >= tgt);
                        unsigned pr = b & (b >> 1);     // bit 2c set iff both ranks ready
                        unsigned m = 0u;
                        #pragma unroll
                        for (int p2 = 0; p2 < 8; ++p2) m |= ((pr >> (2 * p2)) & 1u) << p2;
                        pmask |= m;
                    }
                    if (lane == 0) {
                        mbar_expect_tx(MB + j * 8, CH_B);
                        bulk_g2s(smem_u + SA_OFF + j * CH_B,
                                 &g_h[(size_t)(nb * 8 + g) * 8 * CH_H + cj * CH_H], CH_B, MB + j * 8);
                    }
                }
            }
        }
    }

    // ---- drain, reset counters, readout ----
    grid_barrier();
    if (blk == 0) {
        if (tid < 128) g_cnt[tid] = 0u;
        for (int b = warp; b < BATCH; b += 8) {
            float a = 0.0f;
            #pragma unroll 4
            for (int j = lane; j < HID; j += 32)
                a += g_hlast[b * HID + j] * W_out[j];
            #pragma unroll
            for (int o = 16; o; o >>= 1) a += __shfl_xor_sync(0xFFFFFFFFu, a, o);
            if (lane == 0) out[b] = tanhf(a + b_out[0]);
        }
    }
}

// ---------------- launch ----------------
extern "C" void kernel_launch(void* const* d_in, const int* in_sizes, int n_in,
                              void* d_out, int out_size) {
    const float* x     = (const float*)d_in[0];
    const float* W_ih  = (const float*)d_in[1];
    const float* b_ih  = (const float*)d_in[2];
    const float* W_hh  = (const float*)d_in[3];
    const float* b_hh  = (const float*)d_in[4];
    const float* W_out = (const float*)d_in[5];
    const float* b_out = (const float*)d_in[6];

    cudaFuncSetAttribute(rnn_kernel, cudaFuncAttributeMaxDynamicSharedMemorySize, SMEM_TOTAL);

    xform_kernel<<<T_STEPS + 1, 256>>>(x);
    rnn_kernel<<<NBLK, NTH, SMEM_TOTAL>>>(W_ih, b_ih, W_hh, b_hh, W_out, b_out, (float*)d_out);
}

// round 16
// speedup vs baseline: 1.3251x; 1.0519x over previous
#include <cuda_runtime.h>
#include <cuda_fp16.h>
#include <cstdint>

#define T_STEPS 2048
#define BATCH   128
#define DIM     100
#define HID     1024
#define NBLK    128         // 8 row-groups x 16 col-CTAs
#define NTH     256         // 8 warps: 4 n-groups x 2 k-halves
#define CCOL    64          // columns per CTA
#define CH_H    2176        // halfs per chunk image (16 rows x 136 pitch)
#define CH_B    4352        // bytes per chunk
#define APITCH  272         // bytes per A row (128 halfs + 8 pad)
#define WPITCH_H 1160       // halfs per W row (1152 + 8 pad)
#define WPITCH_B 2320

// ---- smem layout (bytes) ----
#define SA_OFF    0                      // 8 h-chunk slots: 34816
#define SX_OFF    34816                  // 2 x slots: 8704
#define SW_OFF    43520                  // W slice: 64*2320 = 148480
#define SBIAS_OFF 192000                 // 256
#define SPART_OFF 192256                 // partials: 2*4*1024 = 8192
#define SMB_OFF   200448                 // 10 mbars * 8
#define SMEM_TOTAL 200704

// ---------------- device scratch ----------------
__device__ __align__(256) __half g_xT[(size_t)(T_STEPS + 1) * 8 * CH_H]; // [t][group][chunk-image]
__device__ __align__(256) __half g_h[2 * 8 * 8 * CH_H];                  // [buf][group][chunk][2176]
__device__ float  g_hlast[BATCH * HID];
__device__ unsigned g_cnt[8 * 16];       // [group][rank], +4 per step per CTA
__device__ unsigned g_bar_count;
__device__ unsigned g_bar_gen;

// ---------------- PTX helpers ----------------
__device__ __forceinline__ void ldsm_x4(uint32_t addr, uint32_t& r0, uint32_t& r1, uint32_t& r2, uint32_t& r3) {
    asm volatile("ldmatrix.sync.aligned.m8n8.x4.shared.b16 {%0,%1,%2,%3}, [%4];\n"
                 : "=r"(r0), "=r"(r1), "=r"(r2), "=r"(r3) : "r"(addr));
}
__device__ __forceinline__ void mma16816(float* c, uint32_t a0, uint32_t a1, uint32_t a2, uint32_t a3,
                                         uint32_t b0, uint32_t b1) {
    asm volatile("mma.sync.aligned.m16n8k16.row.col.f32.f16.f16.f32 "
                 "{%0,%1,%2,%3},{%4,%5,%6,%7},{%8,%9},{%0,%1,%2,%3};\n"
                 : "+f"(c[0]), "+f"(c[1]), "+f"(c[2]), "+f"(c[3])
                 : "r"(a0), "r"(a1), "r"(a2), "r"(a3), "r"(b0), "r"(b1));
}
__device__ __forceinline__ unsigned ld_acq(const unsigned* p) {
    unsigned v;
    asm volatile("ld.acquire.gpu.u32 %0, [%1];" : "=r"(v) : "l"(p) : "memory");
    return v;
}
__device__ __forceinline__ void mbar_init(uint32_t mbar, uint32_t cnt) {
    asm volatile("mbarrier.init.shared.b64 [%0], %1;" :: "r"(mbar), "r"(cnt) : "memory");
}
__device__ __forceinline__ void mbar_expect_tx(uint32_t mbar, uint32_t bytes) {
    asm volatile("mbarrier.arrive.expect_tx.shared.b64 _, [%0], %1;" :: "r"(mbar), "r"(bytes) : "memory");
}
__device__ __forceinline__ void bulk_g2s(uint32_t dst, const void* src, uint32_t bytes, uint32_t mbar) {
    asm volatile("cp.async.bulk.shared::cluster.global.mbarrier::complete_tx::bytes [%0], [%1], %2, [%3];"
                 :: "r"(dst), "l"(src), "r"(bytes), "r"(mbar) : "memory");
}
__device__ __forceinline__ void mbar_wait(uint32_t mbar, uint32_t parity) {
    uint32_t done;
    do {
        asm volatile("{\n\t.reg .pred p;\n\t"
                     "mbarrier.try_wait.parity.acquire.cta.shared::cta.b64 p, [%1], %2, 0x989680;\n\t"
                     "selp.b32 %0, 1, 0, p;\n\t}"
                     : "=r"(done) : "r"(mbar), "r"(parity) : "memory");
    } while (!done);
}

// ---------------- grid barrier (init/final only) ----------------
__device__ __forceinline__ void grid_barrier() {
    __syncthreads();
    if (threadIdx.x == 0) {
        unsigned my = *(volatile unsigned*)&g_bar_gen;
        __threadfence();
        unsigned a = atomicAdd(&g_bar_count, 1u);
        if (a == NBLK - 1) {
            *(volatile unsigned*)&g_bar_count = 0u;
            __threadfence();
            atomicAdd(&g_bar_gen, 1u);
        } else {
            while (*(volatile unsigned*)&g_bar_gen == my) { __nanosleep(40); }
        }
        __threadfence();
    }
    __syncthreads();
}

// ---------------- kernel 1: x -> [t][group][16 rows x 136 pitch] fp16 ----------------
__global__ void __launch_bounds__(256) xform_kernel(const float* __restrict__ x) {
    int t = blockIdx.x;
    __half* o = g_xT + (size_t)t * 8 * CH_H;
    for (int i = threadIdx.x; i < 8 * CH_H; i += 256) {
        int g = i / CH_H, idx = i % CH_H;
        int row = idx / 136, k = idx % 136;
        float v = 0.0f;
        if (t < T_STEPS && k < DIM)
            v = x[((size_t)t * BATCH + (16 * g + row)) * DIM + k];
        o[i] = __float2half_rn(v);
    }
}

// ---------------- kernel 2: persistent RNN, register-resident W, 4-warp handoff ----------------
__global__ void __launch_bounds__(NTH, 1)
rnn_kernel(const float* __restrict__ W_ih, const float* __restrict__ b_ih,
           const float* __restrict__ W_hh, const float* __restrict__ b_hh,
           const float* __restrict__ W_out, const float* __restrict__ b_out,
           float* __restrict__ out)
{
    extern __shared__ char smem[];
    __half* sW    = (__half*)(smem + SW_OFF);
    float*  sBias = (float*)(smem + SBIAS_OFF);
    float*  sPart = (float*)(smem + SPART_OFF);

    const int tid  = threadIdx.x;
    const int blk  = blockIdx.x;
    const int g    = blk >> 4;       // row group: batch rows [16g, 16g+16)
    const int r    = blk & 15;       // rank: cols [64r, 64r+64)
    const int rot  = r & 7;          // rotated chunk start
    const int lane = tid & 31;
    const int warp = tid >> 5;       // 8 warps
    const int nw   = warp & 3;       // n-group: local cols [16nw, 16nw+16)
    const int ks   = warp >> 2;      // k-half within each 128-k chunk

    uint32_t smem_u = (uint32_t)__cvta_generic_to_shared(smem);
    const uint32_t MB = smem_u + SMB_OFF;     // h mbars 0..7 (by slot), x mbars 8,9

    // ---- prologue: W slice (zero pads then fill) ----
    for (int i = tid; i < (CCOL * WPITCH_B) / 4; i += NTH)
        ((uint32_t*)sW)[i] = 0u;
    __syncthreads();
    for (int i = tid; i < CCOL * HID; i += NTH) {
        int n = i >> 10, k = i & 1023;
        sW[n * WPITCH_H + k] = __float2half_rn(W_hh[(64 * r + n) * HID + k]);
    }
    for (int i = tid; i < CCOL * DIM; i += NTH) {
        int n = i / DIM, d = i % DIM;
        sW[n * WPITCH_H + HID + d] = __float2half_rn(W_ih[(64 * r + n) * DIM + d]);
    }
    if (tid < CCOL) sBias[tid] = b_ih[64 * r + tid] + b_hh[64 * r + tid];

    // zero h buf 0 (incl pads): 17408 uint4 over 32768 threads
    {
        int i = blk * NTH + tid;
        if (i < 17408) ((uint4*)g_h)[i] = make_uint4(0u, 0u, 0u, 0u);
    }
    if (tid == 0) {
        #pragma unroll
        for (int m = 0; m < 10; ++m) mbar_init(MB + m * 8, 1);
    }

    // ---- per-warp addressing ----
    const uint32_t aoff = (lane & 15) * APITCH + ((lane >> 4) * 16) + ks * 128;
    const uint32_t boff = smem_u + SW_OFF
        + (16 * nw + (lane & 7) + ((lane & 16) >> 1)) * WPITCH_B
        + (((lane >> 3) & 1) * 16) + ks * 128;

    // ---- hoist B (weights) into registers: 9 "chunks" x 16 regs, in consumption order ----
    __syncthreads();   // W smem fill complete
    uint32_t breg[144];
    #pragma unroll
    for (int jj = 0; jj < 9; ++jj) {
        uint32_t bb = (jj == 0) ? (boff + 2048) : (boff + (((rot + jj - 1) & 7) * 256));
        #pragma unroll
        for (int s = 0; s < 4; ++s)
            ldsm_x4(bb + s * 32, breg[jj * 16 + s * 4 + 0], breg[jj * 16 + s * 4 + 1],
                                 breg[jj * 16 + s * 4 + 2], breg[jj * 16 + s * 4 + 3]);
    }

    grid_barrier();

    // prologue bulk issues: x0, x1, h(0) chunks in rotated order (slot j <- chunk (rot+j)&7)
    if (tid == 0) {
        mbar_expect_tx(MB + 8 * 8, CH_B);
        bulk_g2s(smem_u + SX_OFF, &g_xT[(size_t)0 * 8 * CH_H + g * CH_H], CH_B, MB + 8 * 8);
        mbar_expect_tx(MB + 9 * 8, CH_B);
        bulk_g2s(smem_u + SX_OFF + CH_B, &g_xT[(size_t)1 * 8 * CH_H + g * CH_H], CH_B, MB + 9 * 8);
        #pragma unroll
        for (int j = 0; j < 8; ++j) {
            const int cj = (rot + j) & 7;
            mbar_expect_tx(MB + j * 8, CH_B);
            bulk_g2s(smem_u + SA_OFF + j * CH_B, &g_h[(size_t)(0 * 8 + g) * 8 * CH_H + cj * CH_H], CH_B, MB + j * 8);
        }
    }

    const int er  = lane >> 2;
    const int ecc = 2 * (lane & 3);
    unsigned* mycnt = &g_cnt[g * 16 + r];
    const unsigned* pollbase = &g_cnt[g * 16];

    // ---- time loop ----
    for (int t = 0; t < T_STEPS; ++t) {
        float acc[8];
        #pragma unroll
        for (int i = 0; i < 8; ++i) acc[i] = 0.0f;

        // x chunk (prefetched one step ahead), B from breg[0..15]
        mbar_wait(MB + (8 + (t & 1)) * 8, (unsigned)((t >> 1) & 1));
        {
            uint32_t ab = smem_u + SX_OFF + (t & 1) * CH_B + aoff;
            #pragma unroll
            for (int s = 0; s < 4; ++s) {
                uint32_t a0, a1, a2, a3;
                ldsm_x4(ab + s * 32, a0, a1, a2, a3);
                mma16816(acc + 0, a0, a1, a2, a3, breg[s * 4 + 0], breg[s * 4 + 1]);
                mma16816(acc + 4, a0, a1, a2, a3, breg[s * 4 + 2], breg[s * 4 + 3]);
            }
        }

        // h chunks in rotated order, gated by slot mbars; B from breg[(j+1)*16...]
        #pragma unroll
        for (int j = 0; j < 8; ++j) {
            mbar_wait(MB + j * 8, (unsigned)(t & 1));
            uint32_t ab = smem_u + SA_OFF + j * CH_B + aoff;
            #pragma unroll
            for (int s = 0; s < 4; ++s) {
                uint32_t a0, a1, a2, a3;
                ldsm_x4(ab + s * 32, a0, a1, a2, a3);
                mma16816(acc + 0, a0, a1, a2, a3, breg[(j + 1) * 16 + s * 4 + 0], breg[(j + 1) * 16 + s * 4 + 1]);
                mma16816(acc + 4, a0, a1, a2, a3, breg[(j + 1) * 16 + s * 4 + 2], breg[(j + 1) * 16 + s * 4 + 3]);
            }
        }

        if (warp >= 4) {
            // store partials, arrive (non-blocking), race ahead
            float* p = sPart + (t & 1) * 1024 + nw * 256 + lane * 8;
            *reinterpret_cast<float4*>(p)     = make_float4(acc[0], acc[1], acc[2], acc[3]);
            *reinterpret_cast<float4*>(p + 4) = make_float4(acc[4], acc[5], acc[6], acc[7]);
            __threadfence_block();
            asm volatile("bar.arrive 1, 256;" ::: "memory");
        } else {
            asm volatile("bar.sync 1, 256;" ::: "memory");
            const float* p = sPart + (t & 1) * 1024 + nw * 256 + lane * 8;
            float4 q0 = *reinterpret_cast<const float4*>(p);
            float4 q1 = *reinterpret_cast<const float4*>(p + 4);

            // warp 0 lane 0: reissue x for t+2 immediately (slot free: all warps passed bar)
            if (warp == 0 && lane == 0 && t + 1 < T_STEPS) {
                mbar_expect_tx(MB + (8 + (t & 1)) * 8, CH_B);
                bulk_g2s(smem_u + SX_OFF + (t & 1) * CH_B,
                         &g_xT[(size_t)(t + 2) * 8 * CH_H + g * CH_H], CH_B, MB + (8 + (t & 1)) * 8);
            }

            const int jl = 16 * nw + ecc;             // local col
            const float bi0 = sBias[jl], bi1 = sBias[jl + 1];
            const float bi4 = sBias[jl + 8], bi5 = sBias[jl + 9];
            float h0 = tanhf(acc[0] + q0.x + bi0);
            float h1 = tanhf(acc[1] + q0.y + bi1);
            float h2 = tanhf(acc[2] + q0.z + bi0);
            float h3 = tanhf(acc[3] + q0.w + bi1);
            float h4 = tanhf(acc[4] + q1.x + bi4);
            float h5 = tanhf(acc[5] + q1.y + bi5);
            float h6 = tanhf(acc[6] + q1.z + bi4);
            float h7 = tanhf(acc[7] + q1.w + bi5);

            const int jc = 64 * r + jl;               // global col
            const int ch = jc >> 7, cc = jc & 127;
            __half* hb = g_h + (size_t)(((t + 1) & 1) * 8 + g) * 8 * CH_H + ch * CH_H;
            *reinterpret_cast<__half2*>(&hb[er * 136 + cc])           = __floats2half2_rn(h0, h1);
            *reinterpret_cast<__half2*>(&hb[(er + 8) * 136 + cc])     = __floats2half2_rn(h2, h3);
            *reinterpret_cast<__half2*>(&hb[er * 136 + cc + 8])       = __floats2half2_rn(h4, h5);
            *reinterpret_cast<__half2*>(&hb[(er + 8) * 136 + cc + 8]) = __floats2half2_rn(h6, h7);
            if (t == T_STEPS - 1) {
                int gr0 = 16 * g + er, gr1 = gr0 + 8;
                g_hlast[gr0 * HID + jc]     = h0;
                g_hlast[gr0 * HID + jc + 1] = h1;
                g_hlast[gr1 * HID + jc]     = h2;
                g_hlast[gr1 * HID + jc + 1] = h3;
                g_hlast[gr0 * HID + jc + 8] = h4;
                g_hlast[gr0 * HID + jc + 9] = h5;
                g_hlast[gr1 * HID + jc + 8] = h6;
                g_hlast[gr1 * HID + jc + 9] = h7;
            }
            __syncwarp();
            if (lane == 0)
                asm volatile("red.release.gpu.global.add.u32 [%0], %1;"
                             :: "l"(mycnt), "r"(1u) : "memory");

            // ---- distributed handoff: warp w gates+issues slots j = w and j = w+4 ----
            if (t + 1 < T_STEPS) {
                const unsigned tgt = 4u * (unsigned)(t + 1);
                const int nb = (t + 1) & 1;
                unsigned pmask = 0u;   // bit c: chunk c's producer pair (ranks 2c,2c+1) ready
                #pragma unroll
                for (int jj = 0; jj < 2; ++jj) {
                    const int j = warp + jj * 4;        // slot index
                    const int cj = (rot + j) & 7;       // chunk id
                    while (!((pmask >> cj) & 1u)) {
                        unsigned v = (lane < 16) ? ld_acq(pollbase + lane) : tgt;
                        unsigned b = __ballot_sync(0xFFFFFFFFu, v >= tgt);
                        unsigned pr = b & (b >> 1);     // bit 2c set iff both ranks ready
                        unsigned m = 0u;
                        #pragma unroll
                        for (int p2 = 0; p2 < 8; ++p2) m |= ((pr >> (2 * p2)) & 1u) << p2;
                        pmask |= m;
                    }
                    if (lane == 0) {
                        mbar_expect_tx(MB + j * 8, CH_B);
                        bulk_g2s(smem_u + SA_OFF + j * CH_B,
                                 &g_h[(size_t)(nb * 8 + g) * 8 * CH_H + cj * CH_H], CH_B, MB + j * 8);
                    }
                }
            }
        }
    }

    // ---- drain, reset counters, readout ----
    grid_barrier();
    if (blk == 0) {
        if (tid < 128) g_cnt[tid] = 0u;
        for (int b = warp; b < BATCH; b += 8) {
            float a = 0.0f;
            #pragma unroll 4
            for (int j = lane; j < HID; j += 32)
                a += g_hlast[b * HID + j] * W_out[j];
            #pragma unroll
            for (int o = 16; o; o >>= 1) a += __shfl_xor_sync(0xFFFFFFFFu, a, o);
            if (lane == 0) out[b] = tanhf(a + b_out[0]);
        }
    }
}

// ---------------- launch ----------------
extern "C" void kernel_launch(void* const* d_in, const int* in_sizes, int n_in,
                              void* d_out, int out_size) {
    const float* x     = (const float*)d_in[0];
    const float* W_ih  = (const float*)d_in[1];
    const float* b_ih  = (const float*)d_in[2];
    const float* W_hh  = (const float*)d_in[3];
    const float* b_hh  = (const float*)d_in[4];
    const float* W_out = (const float*)d_in[5];
    const float* b_out = (const float*)d_in[6];

    cudaFuncSetAttribute(rnn_kernel, cudaFuncAttributeMaxDynamicSharedMemorySize, SMEM_TOTAL);

    xform_kernel<<<T_STEPS + 1, 256>>>(x);
    rnn_kernel<<<NBLK, NTH, SMEM_TOTAL>>>(W_ih, b_ih, W_hh, b_hh, W_out, b_out, (float*)d_out);
}